// round 11
// baseline (speedup 1.0000x reference)
#include <cuda_runtime.h>
#include <cstdint>

// Problem constants
#define B_   2
#define L_   2048
#define D_   2048
#define NH_  16
#define HD_  128
#define BH_  (B_ * NH_)
#define ML_  (B_ * L_)          // 4096 rows for projections

// ---------------------------------------------------------------------------
// Scratch (static device allocations; no cudaMalloc allowed)
// ---------------------------------------------------------------------------
__device__ __align__(1024) float g_q[(size_t)ML_ * D_];
__device__ __align__(1024) float g_k[(size_t)ML_ * D_];
__device__ __align__(1024) float g_v[(size_t)ML_ * D_];
__device__ __align__(1024) float g_attn[(size_t)ML_ * D_];
__device__ __align__(1024) float g_hsr[(size_t)ML_ * D_];
__device__ __align__(1024) float g_wqr[(size_t)D_ * D_];
__device__ __align__(1024) float g_wkr[(size_t)D_ * D_];
__device__ __align__(1024) float g_wvr[(size_t)D_ * D_];
__device__ __align__(1024) float g_wor[(size_t)D_ * D_];

// attention scale folded with log2(e) so softmax uses exp2
#define ATT_QSCALE (0.08838834764831845f * 1.4426950408889634f)

// ---------------------------------------------------------------------------
// Helpers
// ---------------------------------------------------------------------------
__device__ __forceinline__ uint32_t smem_u32(const void* p) {
    uint32_t a;
    asm("{ .reg .u64 t; cvta.to.shared.u64 t, %1; cvt.u32.u64 %0, t; }"
        : "=r"(a) : "l"(p));
    return a;
}

__device__ __forceinline__ float tf32r(float x) {
    uint32_t u;
    asm("cvt.rna.tf32.f32 %0, %1;" : "=r"(u) : "f"(x));
    return __uint_as_float(u);
}

#define CP_ASYNC16(dst, src) \
    asm volatile("cp.async.cg.shared.global [%0], [%1], 16;" \
                 :: "r"(dst), "l"(src) : "memory")
#define CP_COMMIT() asm volatile("cp.async.commit_group;" ::: "memory")
#define CP_WAIT1()  asm volatile("cp.async.wait_group 1;" ::: "memory")
#define CP_WAIT0()  asm volatile("cp.async.wait_group 0;" ::: "memory")

// mma.sync m16n8k8 tf32: D += A*B, A row-major m16k8, B col-major k8n8
#define MMA_TF32_16N8K8(c, a, b) \
    asm volatile("mma.sync.aligned.m16n8k8.row.col.f32.tf32.tf32.f32 " \
                 "{%0,%1,%2,%3}, {%4,%5,%6,%7}, {%8,%9}, {%0,%1,%2,%3};" \
                 : "+f"((c)[0]), "+f"((c)[1]), "+f"((c)[2]), "+f"((c)[3]) \
                 : "r"((a)[0]), "r"((a)[1]), "r"((a)[2]), "r"((a)[3]), \
                   "r"((b)[0]), "r"((b)[1]))

// ---------------------------------------------------------------------------
// Round-to-tf32 copy kernel (rounds GEMM operands to tf32-nearest once)
// ---------------------------------------------------------------------------
__global__ void round_tf32_kernel(const float* __restrict__ in,
                                  float* __restrict__ out, int n4)
{
    int i = blockIdx.x * blockDim.x + threadIdx.x;
    int stride = gridDim.x * blockDim.x;
    for (; i < n4; i += stride) {
        float4 v = ((const float4*)in)[i];
        v.x = tf32r(v.x); v.y = tf32r(v.y);
        v.z = tf32r(v.z); v.w = tf32r(v.w);
        ((float4*)out)[i] = v;
    }
}

// ---------------------------------------------------------------------------
// HMMA tf32 GEMM: C[M,2048] = A[M,2048] @ W[2048,2048]^T + bias
// (unchanged from the passing R9/R10 kernel)
// ---------------------------------------------------------------------------
#define GBK     32
#define GSTG    3
#define ROWPAD  36
#define TILE_FLOATS (128 * ROWPAD)            // 4608 floats
#define STAGE_FLOATS (2 * TILE_FLOATS)        // 9216 floats
#define GEMM_SMEM (GSTG * STAGE_FLOATS * 4)   // 110592 bytes

__global__ __launch_bounds__(256, 2)
void gemm_tf32mma(const float* __restrict__ A,
                  const float* __restrict__ W0, const float* __restrict__ W1,
                  const float* __restrict__ W2,
                  const float* __restrict__ b0, const float* __restrict__ b1,
                  const float* __restrict__ b2,
                  float* __restrict__ C0, float* __restrict__ C1,
                  float* __restrict__ C2,
                  float scale0, int do_round)
{
    extern __shared__ __align__(1024) float smf[];
    const uint32_t sb = smem_u32(smf);

    const int z = blockIdx.z;
    const float* W    = (z == 0) ? W0 : (z == 1) ? W1 : W2;
    const float* bias = (z == 0) ? b0 : (z == 1) ? b1 : b2;
    float*       C    = (z == 0) ? C0 : (z == 1) ? C1 : C2;
    const float  esc  = (z == 0) ? scale0 : 1.0f;

    const int tid  = threadIdx.x;
    const int wid  = tid >> 5;
    const int lane = tid & 31;
    const int g    = lane >> 2;
    const int tg   = lane & 3;
    const int wr   = wid >> 1;
    const int wc   = wid & 1;

    const int row0 = blockIdx.y * 128;
    const int col0 = blockIdx.x * 128;
    const int K    = D_;
    const int NIT  = K / GBK;                  // 64

    const float* Ab = A + (size_t)row0 * K;
    const float* Wb = W + (size_t)col0 * K;

    int c_isB[8], c_row[8], c_c4[8];
    #pragma unroll
    for (int p = 0; p < 8; p++) {
        int idx = p * 256 + tid;
        c_isB[p] = idx >= 1024;
        int id2  = idx & 1023;
        c_row[p] = id2 >> 3;
        c_c4[p]  = id2 & 7;
    }

    auto issue = [&](int s, int it) {
        const int k0 = it * GBK;
        #pragma unroll
        for (int p = 0; p < 8; p++) {
            const float* src = (c_isB[p] ? Wb : Ab)
                               + (size_t)c_row[p] * K + k0 + c_c4[p] * 4;
            uint32_t dst = sb + (uint32_t)(s * STAGE_FLOATS
                              + c_isB[p] * TILE_FLOATS
                              + c_row[p] * ROWPAD + c_c4[p] * 4) * 4u;
            CP_ASYNC16(dst, src);
        }
    };

    float acc[2][8][4];
    #pragma unroll
    for (int mt = 0; mt < 2; mt++)
        #pragma unroll
        for (int nt = 0; nt < 8; nt++)
            #pragma unroll
            for (int e = 0; e < 4; e++) acc[mt][nt][e] = 0.0f;

    issue(0, 0); CP_COMMIT();
    issue(1, 1); CP_COMMIT();

    int s = 0;
    for (int it = 0; it < NIT; it++) {
        CP_WAIT1();
        __syncthreads();

        const float* As = smf + s * STAGE_FLOATS;
        const float* Bs = As + TILE_FLOATS;

        #pragma unroll
        for (int ks = 0; ks < 4; ks++) {
            const int kb = ks * 8;
            uint32_t af[2][4];
            #pragma unroll
            for (int mt = 0; mt < 2; mt++) {
                const int rb = wr * 32 + mt * 16;
                af[mt][0] = __float_as_uint(As[(rb + g)     * ROWPAD + kb + tg]);
                af[mt][1] = __float_as_uint(As[(rb + g + 8) * ROWPAD + kb + tg]);
                af[mt][2] = __float_as_uint(As[(rb + g)     * ROWPAD + kb + tg + 4]);
                af[mt][3] = __float_as_uint(As[(rb + g + 8) * ROWPAD + kb + tg + 4]);
            }
            uint32_t bf[8][2];
            #pragma unroll
            for (int nt = 0; nt < 8; nt++) {
                const int cb = wc * 64 + nt * 8;
                bf[nt][0] = __float_as_uint(Bs[(cb + g) * ROWPAD + kb + tg]);
                bf[nt][1] = __float_as_uint(Bs[(cb + g) * ROWPAD + kb + tg + 4]);
            }
            #pragma unroll
            for (int mt = 0; mt < 2; mt++)
                #pragma unroll
                for (int nt = 0; nt < 8; nt++)
                    MMA_TF32_16N8K8(acc[mt][nt], af[mt], bf[nt]);
        }

        __syncthreads();
        if (it + 2 < NIT) {
            int sn = s + 2; if (sn >= GSTG) sn -= GSTG;
            issue(sn, it + 2);
        }
        CP_COMMIT();
        s = (s + 1 == GSTG) ? 0 : s + 1;
    }

    // epilogue: bias add (+ optional scale + tf32 round) + store
    #pragma unroll
    for (int mt = 0; mt < 2; mt++) {
        const int r0 = row0 + wr * 32 + mt * 16 + g;
        #pragma unroll
        for (int nt = 0; nt < 8; nt++) {
            const int c = col0 + wc * 64 + nt * 8 + tg * 2;
            float2 bb = *(const float2*)&bias[c];
            float2 o0 = make_float2((acc[mt][nt][0] + bb.x) * esc,
                                    (acc[mt][nt][1] + bb.y) * esc);
            float2 o1 = make_float2((acc[mt][nt][2] + bb.x) * esc,
                                    (acc[mt][nt][3] + bb.y) * esc);
            if (do_round) {
                o0.x = tf32r(o0.x); o0.y = tf32r(o0.y);
                o1.x = tf32r(o1.x); o1.y = tf32r(o1.y);
            }
            *(float2*)&C[(size_t)r0 * D_ + c]       = o0;
            *(float2*)&C[(size_t)(r0 + 8) * D_ + c] = o1;
        }
    }
}

// ---------------------------------------------------------------------------
// Fast exp2 on the FMA pipe. |err| ~2e-6 rel.
// ---------------------------------------------------------------------------
__device__ __forceinline__ float exp2p(float y) {
    y = fmaxf(y, -120.0f);
    float t = y + 12582912.0f;
    int   i = __float_as_int(t);
    float f = y - (t - 12582912.0f);
    float p = 1.3333558e-3f;
    p = fmaf(p, f, 9.6181291e-3f);
    p = fmaf(p, f, 5.5504109e-2f);
    p = fmaf(p, f, 2.4022651e-1f);
    p = fmaf(p, f, 6.9314718e-1f);
    p = fmaf(p, f, 1.0f);
    return __int_as_float(__float_as_int(p) + (i << 23));
}

// ---------------------------------------------------------------------------
// Flash attention, tf32 mma.sync, causal. BM=128, BN=64, HD=128, 8 warps.
// Low-register design: Q lives in smem (A-frags re-read per tile), BN=64
// halves the score-fragment count -> peak live regs ~130 (no spills).
// g_q/g_k/g_v are pre-rounded (Q pre-scaled) by the GEMM epilogue.
//   Qs 128x136 | Kb 64x136 | Vb 64x136 | Ps 128x68   = 174,080 B smem
// cp.async group pipeline: V(t) loads during QK(t), K(t+1) during PV(t).
// ---------------------------------------------------------------------------
#define QST 136     // Q/K/V row stride (floats); 136 % 32 == 8
#define PST2 68     // Ps stride; 68 % 32 == 4

extern __shared__ float satt[];

__global__ __launch_bounds__(256, 1)
void attn_mma(const float* __restrict__ Q, const float* __restrict__ K,
              const float* __restrict__ V, float* __restrict__ O)
{
    float* Qs = satt;                            // 128 x 136
    float* Kb = satt + 128 * QST;                // 64 x 136
    float* Vb = Kb + 64 * QST;                   // 64 x 136
    float* Ps = Vb + 64 * QST;                   // 128 x 68
    const uint32_t sbase = smem_u32(satt);
    const uint32_t QsA = sbase;
    const uint32_t KbA = sbase + 128u * QST * 4u;
    const uint32_t VbA = KbA + 64u * QST * 4u;

    const int tid  = threadIdx.x;
    const int w    = tid >> 5;
    const int lane = tid & 31;
    const int g    = lane >> 2;
    const int tg   = lane & 3;
    const int rb   = w * 16;

    const int qb = gridDim.x - 1 - blockIdx.x;   // heavy-first schedule
    const int bh = blockIdx.y;
    const int b  = bh / NH_;
    const int h  = bh % NH_;
    const int q0 = qb * 128;
    const size_t base = (size_t)b * L_ * D_ + (size_t)h * HD_;

    // 64x128-float tile = 2048 16B chunks, 8 per thread
    auto load64 = [&](uint32_t dstA, const float* src) {
        #pragma unroll
        for (int p = 0; p < 8; p++) {
            int idx = p * 256 + tid;
            int r   = idx >> 5;
            int c   = idx & 31;
            CP_ASYNC16(dstA + (uint32_t)(r * QST + c * 4) * 4u,
                       src + (size_t)r * D_ + c * 4);
        }
    };

    // ---- prologue: Q (once) and K(0) ----
    #pragma unroll
    for (int p = 0; p < 16; p++) {
        int idx = p * 256 + tid;
        int r   = idx >> 5;
        int c   = idx & 31;
        CP_ASYNC16(QsA + (uint32_t)(r * QST + c * 4) * 4u,
                   Q + base + (size_t)(q0 + r) * D_ + c * 4);
    }
    CP_COMMIT();                                 // G: Q
    load64(KbA, K + base);                       // G: K0
    CP_COMMIT();

    float o_[16][4];
    float m0 = -3.0e38f, m1 = -3.0e38f, l0 = 0.0f, l1 = 0.0f;
    #pragma unroll
    for (int nt = 0; nt < 16; nt++)
        #pragma unroll
        for (int e = 0; e < 4; e++) o_[nt][e] = 0.0f;

    const int TEND = 2 * qb + 1;                 // 64-key tiles
    for (int t = 0; t <= TEND; t++) {
        const int n0 = t * 64;

        __syncthreads();                         // Vb free (prev PV done)
        load64(VbA, V + base + (size_t)n0 * D_);
        CP_COMMIT();
        CP_WAIT1();                              // Q(+K(t)) landed; V(t) in flight
        __syncthreads();

        // ---- S = Q K^T (scores in log2 units; Q pre-scaled) ----
        float sf[8][4];
        #pragma unroll
        for (int nt = 0; nt < 8; nt++)
            #pragma unroll
            for (int e = 0; e < 4; e++) sf[nt][e] = 0.0f;

        #pragma unroll
        for (int ks = 0; ks < 16; ks++) {
            const int kb = ks * 8;
            uint32_t af[4];
            af[0] = __float_as_uint(Qs[(rb + g)     * QST + kb + tg]);
            af[1] = __float_as_uint(Qs[(rb + g + 8) * QST + kb + tg]);
            af[2] = __float_as_uint(Qs[(rb + g)     * QST + kb + tg + 4]);
            af[3] = __float_as_uint(Qs[(rb + g + 8) * QST + kb + tg + 4]);
            #pragma unroll
            for (int nt = 0; nt < 8; nt++) {
                uint32_t bf[2];
                bf[0] = __float_as_uint(Kb[(nt * 8 + g) * QST + kb + tg]);
                bf[1] = __float_as_uint(Kb[(nt * 8 + g) * QST + kb + tg + 4]);
                MMA_TF32_16N8K8(sf[nt], af, bf);
            }
        }

        // ---- causal mask (only the last two 64-key tiles can straddle) ----
        if (t >= 2 * qb) {
            const int gr0 = q0 + rb + g, gr1 = gr0 + 8;
            #pragma unroll
            for (int nt = 0; nt < 8; nt++) {
                const int gc = n0 + nt * 8 + 2 * tg;
                if (gr0 < gc)     sf[nt][0] = -1.0e30f;
                if (gr0 < gc + 1) sf[nt][1] = -1.0e30f;
                if (gr1 < gc)     sf[nt][2] = -1.0e30f;
                if (gr1 < gc + 1) sf[nt][3] = -1.0e30f;
            }
        }

        // ---- online softmax on fragments ----
        float ml0 = -3.0e38f, ml1 = -3.0e38f;
        #pragma unroll
        for (int nt = 0; nt < 8; nt++) {
            ml0 = fmaxf(ml0, fmaxf(sf[nt][0], sf[nt][1]));
            ml1 = fmaxf(ml1, fmaxf(sf[nt][2], sf[nt][3]));
        }
        ml0 = fmaxf(ml0, __shfl_xor_sync(0xffffffffu, ml0, 1));
        ml0 = fmaxf(ml0, __shfl_xor_sync(0xffffffffu, ml0, 2));
        ml1 = fmaxf(ml1, __shfl_xor_sync(0xffffffffu, ml1, 1));
        ml1 = fmaxf(ml1, __shfl_xor_sync(0xffffffffu, ml1, 2));

        const float mn0 = fmaxf(m0, ml0), mn1 = fmaxf(m1, ml1);
        const float a0 = exp2p(m0 - mn0), a1 = exp2p(m1 - mn1);
        float rs0 = 0.0f, rs1 = 0.0f;
        #pragma unroll
        for (int nt = 0; nt < 8; nt++) {
            float p0 = exp2p(sf[nt][0] - mn0);
            float p1 = exp2p(sf[nt][1] - mn0);
            float p2 = exp2p(sf[nt][2] - mn1);
            float p3 = exp2p(sf[nt][3] - mn1);
            rs0 += p0 + p1; rs1 += p2 + p3;
            *(float2*)&Ps[(rb + g)     * PST2 + nt * 8 + 2 * tg] =
                make_float2(tf32r(p0), tf32r(p1));
            *(float2*)&Ps[(rb + g + 8) * PST2 + nt * 8 + 2 * tg] =
                make_float2(tf32r(p2), tf32r(p3));
        }
        rs0 += __shfl_xor_sync(0xffffffffu, rs0, 1);
        rs0 += __shfl_xor_sync(0xffffffffu, rs0, 2);
        rs1 += __shfl_xor_sync(0xffffffffu, rs1, 1);
        rs1 += __shfl_xor_sync(0xffffffffu, rs1, 2);
        l0 = l0 * a0 + rs0; l1 = l1 * a1 + rs1;
        m0 = mn0; m1 = mn1;
        #pragma unroll
        for (int nt = 0; nt < 16; nt++) {
            o_[nt][0] *= a0; o_[nt][1] *= a0;
            o_[nt][2] *= a1; o_[nt][3] *= a1;
        }

        __syncthreads();                         // Kb free (QK reads done)
        if (t < TEND) {
            load64(KbA, K + base + (size_t)(n0 + 64) * D_);   // K(t+1)
            CP_COMMIT();
            CP_WAIT1();                          // V(t) landed; K(t+1) in flight
        } else {
            CP_WAIT0();                          // V(t) landed
        }
        __syncthreads();

        // ---- O += P @ V  (V natural; B-frag banks 8tg+g, conflict-free) ----
        #pragma unroll
        for (int ks = 0; ks < 8; ks++) {
            const int kb = ks * 8;
            uint32_t af[4];
            af[0] = __float_as_uint(Ps[(rb + g)     * PST2 + kb + tg]);
            af[1] = __float_as_uint(Ps[(rb + g + 8) * PST2 + kb + tg]);
            af[2] = __float_as_uint(Ps[(rb + g)     * PST2 + kb + tg + 4]);
            af[3] = __float_as_uint(Ps[(rb + g + 8) * PST2 + kb + tg + 4]);
            #pragma unroll
            for (int nt = 0; nt < 16; nt++) {
                uint32_t bf[2];
                bf[0] = __float_as_uint(Vb[(kb + tg)     * QST + nt * 8 + g]);
                bf[1] = __float_as_uint(Vb[(kb + tg + 4) * QST + nt * 8 + g]);
                MMA_TF32_16N8K8(o_[nt], af, bf);
            }
        }
    }

    // ---- epilogue: normalize + tf32-round + write ----
    const float inv0 = 1.0f / l0, inv1 = 1.0f / l1;
    const int gr0 = q0 + rb + g, gr1 = gr0 + 8;
    #pragma unroll
    for (int nt = 0; nt < 16; nt++) {
        const int c = nt * 8 + 2 * tg;
        *(float2*)&O[base + (size_t)gr0 * D_ + c] =
            make_float2(tf32r(o_[nt][0] * inv0), tf32r(o_[nt][1] * inv0));
        *(float2*)&O[base + (size_t)gr1 * D_ + c] =
            make_float2(tf32r(o_[nt][2] * inv1), tf32r(o_[nt][3] * inv1));
    }
}

#define ATTN_SMEM ((128 * QST + 2 * 64 * QST + 128 * PST2) * 4)  // 174,080 B

// ---------------------------------------------------------------------------
// Launcher
// ---------------------------------------------------------------------------
extern "C" void kernel_launch(void* const* d_in, const int* in_sizes, int n_in,
                              void* d_out, int out_size)
{
    const float* hs = (const float*)d_in[0];
    const float* Wq = (const float*)d_in[1];
    const float* bq = (const float*)d_in[2];
    const float* Wk = (const float*)d_in[3];
    const float* bk = (const float*)d_in[4];
    const float* Wv = (const float*)d_in[5];
    const float* bv = (const float*)d_in[6];
    const float* Wo = (const float*)d_in[7];
    const float* bo = (const float*)d_in[8];
    float* out = (float*)d_out;

    float *q, *k, *v, *attn, *hsr, *wqr, *wkr, *wvr, *wor;
    cudaGetSymbolAddress((void**)&q,    g_q);
    cudaGetSymbolAddress((void**)&k,    g_k);
    cudaGetSymbolAddress((void**)&v,    g_v);
    cudaGetSymbolAddress((void**)&attn, g_attn);
    cudaGetSymbolAddress((void**)&hsr,  g_hsr);
    cudaGetSymbolAddress((void**)&wqr,  g_wqr);
    cudaGetSymbolAddress((void**)&wkr,  g_wkr);
    cudaGetSymbolAddress((void**)&wvr,  g_wvr);
    cudaGetSymbolAddress((void**)&wor,  g_wor);

    // round all GEMM operands to tf32-nearest
    const int nHS4 = ML_ * D_ / 4;
    const int nW4  = D_ * D_ / 4;
    round_tf32_kernel<<<2048, 256>>>(hs, hsr, nHS4);
    round_tf32_kernel<<<2048, 256>>>(Wq, wqr, nW4);
    round_tf32_kernel<<<2048, 256>>>(Wk, wkr, nW4);
    round_tf32_kernel<<<2048, 256>>>(Wv, wvr, nW4);
    round_tf32_kernel<<<2048, 256>>>(Wo, wor, nW4);

    cudaFuncSetAttribute(gemm_tf32mma,
                         cudaFuncAttributeMaxDynamicSharedMemorySize, GEMM_SMEM);

    // fused Q/K/V projection: outputs pre-rounded; Q pre-scaled
    dim3 gqkv(D_ / 128, ML_ / 128, 3);   // (16, 32, 3)
    gemm_tf32mma<<<gqkv, 256, GEMM_SMEM>>>(hsr, wqr, wkr, wvr,
                                           bq, bk, bv, q, k, v,
                                           (float)ATT_QSCALE, 1);

    cudaFuncSetAttribute(attn_mma,
                         cudaFuncAttributeMaxDynamicSharedMemorySize,
                         ATTN_SMEM);
    attn_mma<<<dim3(L_ / 128, BH_), 256, ATTN_SMEM>>>(q, k, v, attn);

    // O-projection: plain fp32 output, no scale, no rounding
    dim3 go(D_ / 128, ML_ / 128, 1);
    gemm_tf32mma<<<go, 256, GEMM_SMEM>>>(attn, wor, wor, wor,
                                         bo, bo, bo, out, out, out,
                                         1.0f, 0);
}

// round 12
// speedup vs baseline: 1.0314x; 1.0314x over previous
#include <cuda_runtime.h>
#include <cstdint>

// Problem constants
#define B_   2
#define L_   2048
#define D_   2048
#define NH_  16
#define HD_  128
#define BH_  (B_ * NH_)
#define ML_  (B_ * L_)          // 4096 rows for projections

// ---------------------------------------------------------------------------
// Scratch (static device allocations; no cudaMalloc allowed)
// ---------------------------------------------------------------------------
__device__ __align__(1024) float g_q[(size_t)ML_ * D_];
__device__ __align__(1024) float g_k[(size_t)ML_ * D_];
__device__ __align__(1024) float g_v[(size_t)ML_ * D_];
__device__ __align__(1024) float g_attn[(size_t)ML_ * D_];
__device__ __align__(1024) float g_hsr[(size_t)ML_ * D_];
__device__ __align__(1024) float g_wqr[(size_t)D_ * D_];
__device__ __align__(1024) float g_wkr[(size_t)D_ * D_];
__device__ __align__(1024) float g_wvr[(size_t)D_ * D_];
__device__ __align__(1024) float g_wor[(size_t)D_ * D_];

// attention scale folded with log2(e) so softmax uses exp2
#define ATT_QSCALE (0.08838834764831845f * 1.4426950408889634f)

// ---------------------------------------------------------------------------
// Helpers
// ---------------------------------------------------------------------------
__device__ __forceinline__ uint32_t smem_u32(const void* p) {
    uint32_t a;
    asm("{ .reg .u64 t; cvta.to.shared.u64 t, %1; cvt.u32.u64 %0, t; }"
        : "=r"(a) : "l"(p));
    return a;
}

__device__ __forceinline__ float tf32r(float x) {
    uint32_t u;
    asm("cvt.rna.tf32.f32 %0, %1;" : "=r"(u) : "f"(x));
    return __uint_as_float(u);
}

#define CP_ASYNC16(dst, src) \
    asm volatile("cp.async.cg.shared.global [%0], [%1], 16;" \
                 :: "r"(dst), "l"(src) : "memory")
#define CP_COMMIT() asm volatile("cp.async.commit_group;" ::: "memory")
#define CP_WAIT1()  asm volatile("cp.async.wait_group 1;" ::: "memory")
#define CP_WAIT0()  asm volatile("cp.async.wait_group 0;" ::: "memory")

// mma.sync m16n8k8 tf32: D += A*B, A row-major m16k8, B col-major k8n8
#define MMA_TF32_16N8K8(c, a, b) \
    asm volatile("mma.sync.aligned.m16n8k8.row.col.f32.tf32.tf32.f32 " \
                 "{%0,%1,%2,%3}, {%4,%5,%6,%7}, {%8,%9}, {%0,%1,%2,%3};" \
                 : "+f"((c)[0]), "+f"((c)[1]), "+f"((c)[2]), "+f"((c)[3]) \
                 : "r"((a)[0]), "r"((a)[1]), "r"((a)[2]), "r"((a)[3]), \
                   "r"((b)[0]), "r"((b)[1]))

// ---------------------------------------------------------------------------
// Round-to-tf32 copy kernel, all 5 tensors in ONE launch (gridDim.z picks).
// ---------------------------------------------------------------------------
__global__ void round_tf32_all(const float* __restrict__ i0, float* __restrict__ o0, int n0,
                               const float* __restrict__ i1, float* __restrict__ o1, int n1,
                               const float* __restrict__ i2, float* __restrict__ o2, int n2,
                               const float* __restrict__ i3, float* __restrict__ o3, int n3,
                               const float* __restrict__ i4, float* __restrict__ o4, int n4)
{
    const int z = blockIdx.z;
    const float* in  = (z == 0) ? i0 : (z == 1) ? i1 : (z == 2) ? i2
                      : (z == 3) ? i3 : i4;
    float*       out = (z == 0) ? o0 : (z == 1) ? o1 : (z == 2) ? o2
                      : (z == 3) ? o3 : o4;
    const int    n   = (z == 0) ? n0 : (z == 1) ? n1 : (z == 2) ? n2
                      : (z == 3) ? n3 : n4;

    int i = blockIdx.x * blockDim.x + threadIdx.x;
    int stride = gridDim.x * blockDim.x;
    for (; i < n; i += stride) {
        float4 v = ((const float4*)in)[i];
        v.x = tf32r(v.x); v.y = tf32r(v.y);
        v.z = tf32r(v.z); v.w = tf32r(v.w);
        ((float4*)out)[i] = v;
    }
}

// ---------------------------------------------------------------------------
// HMMA tf32 GEMM: C[M,2048] = A[M,2048] @ W[2048,2048]^T + bias
// BM=BN=128, BK=32, 3-stage cp.async pipeline, SINGLE sync per k-iter:
// the top-of-iteration barrier transitively guarantees all warps finished
// reading the stage being overwritten (s+2 mod 3, last read at iter it-1).
// gridDim.z picks one of up to 3 (W, bias, C) instances (fused QKV launch).
// ---------------------------------------------------------------------------
#define GBK     32
#define GSTG    3
#define ROWPAD  36
#define TILE_FLOATS (128 * ROWPAD)            // 4608 floats
#define STAGE_FLOATS (2 * TILE_FLOATS)        // 9216 floats
#define GEMM_SMEM (GSTG * STAGE_FLOATS * 4)   // 110592 bytes

__global__ __launch_bounds__(256, 2)
void gemm_tf32mma(const float* __restrict__ A,
                  const float* __restrict__ W0, const float* __restrict__ W1,
                  const float* __restrict__ W2,
                  const float* __restrict__ b0, const float* __restrict__ b1,
                  const float* __restrict__ b2,
                  float* __restrict__ C0, float* __restrict__ C1,
                  float* __restrict__ C2,
                  float scale0, int do_round)
{
    extern __shared__ __align__(1024) float smf[];
    const uint32_t sb = smem_u32(smf);

    const int z = blockIdx.z;
    const float* W    = (z == 0) ? W0 : (z == 1) ? W1 : W2;
    const float* bias = (z == 0) ? b0 : (z == 1) ? b1 : b2;
    float*       C    = (z == 0) ? C0 : (z == 1) ? C1 : C2;
    const float  esc  = (z == 0) ? scale0 : 1.0f;

    const int tid  = threadIdx.x;
    const int wid  = tid >> 5;
    const int lane = tid & 31;
    const int g    = lane >> 2;
    const int tg   = lane & 3;
    const int wr   = wid >> 1;
    const int wc   = wid & 1;

    const int row0 = blockIdx.y * 128;
    const int col0 = blockIdx.x * 128;
    const int K    = D_;
    const int NIT  = K / GBK;                  // 64

    const float* Ab = A + (size_t)row0 * K;
    const float* Wb = W + (size_t)col0 * K;

    int c_isB[8], c_row[8], c_c4[8];
    #pragma unroll
    for (int p = 0; p < 8; p++) {
        int idx = p * 256 + tid;
        c_isB[p] = idx >= 1024;
        int id2  = idx & 1023;
        c_row[p] = id2 >> 3;
        c_c4[p]  = id2 & 7;
    }

    auto issue = [&](int s, int it) {
        const int k0 = it * GBK;
        #pragma unroll
        for (int p = 0; p < 8; p++) {
            const float* src = (c_isB[p] ? Wb : Ab)
                               + (size_t)c_row[p] * K + k0 + c_c4[p] * 4;
            uint32_t dst = sb + (uint32_t)(s * STAGE_FLOATS
                              + c_isB[p] * TILE_FLOATS
                              + c_row[p] * ROWPAD + c_c4[p] * 4) * 4u;
            CP_ASYNC16(dst, src);
        }
    };

    float acc[2][8][4];
    #pragma unroll
    for (int mt = 0; mt < 2; mt++)
        #pragma unroll
        for (int nt = 0; nt < 8; nt++)
            #pragma unroll
            for (int e = 0; e < 4; e++) acc[mt][nt][e] = 0.0f;

    issue(0, 0); CP_COMMIT();
    issue(1, 1); CP_COMMIT();

    int s = 0;
    for (int it = 0; it < NIT; it++) {
        CP_WAIT1();
        __syncthreads();                       // the ONE barrier per iter

        // issue next stage first (target stage's readers finished at it-1,
        // guaranteed by the barrier above)
        if (it + 2 < NIT) {
            int sn = s + 2; if (sn >= GSTG) sn -= GSTG;
            issue(sn, it + 2);
        }
        CP_COMMIT();                           // empty commits keep accounting

        const float* As = smf + s * STAGE_FLOATS;
        const float* Bs = As + TILE_FLOATS;

        #pragma unroll
        for (int ks = 0; ks < 4; ks++) {
            const int kb = ks * 8;
            uint32_t af[2][4];
            #pragma unroll
            for (int mt = 0; mt < 2; mt++) {
                const int rb = wr * 32 + mt * 16;
                af[mt][0] = __float_as_uint(As[(rb + g)     * ROWPAD + kb + tg]);
                af[mt][1] = __float_as_uint(As[(rb + g + 8) * ROWPAD + kb + tg]);
                af[mt][2] = __float_as_uint(As[(rb + g)     * ROWPAD + kb + tg + 4]);
                af[mt][3] = __float_as_uint(As[(rb + g + 8) * ROWPAD + kb + tg + 4]);
            }
            uint32_t bf[8][2];
            #pragma unroll
            for (int nt = 0; nt < 8; nt++) {
                const int cb = wc * 64 + nt * 8;
                bf[nt][0] = __float_as_uint(Bs[(cb + g) * ROWPAD + kb + tg]);
                bf[nt][1] = __float_as_uint(Bs[(cb + g) * ROWPAD + kb + tg + 4]);
            }
            #pragma unroll
            for (int mt = 0; mt < 2; mt++)
                #pragma unroll
                for (int nt = 0; nt < 8; nt++)
                    MMA_TF32_16N8K8(acc[mt][nt], af[mt], bf[nt]);
        }

        s = (s + 1 == GSTG) ? 0 : s + 1;
    }

    // epilogue: bias add (+ optional scale + tf32 round) + store
    #pragma unroll
    for (int mt = 0; mt < 2; mt++) {
        const int r0 = row0 + wr * 32 + mt * 16 + g;
        #pragma unroll
        for (int nt = 0; nt < 8; nt++) {
            const int c = col0 + wc * 64 + nt * 8 + tg * 2;
            float2 bb = *(const float2*)&bias[c];
            float2 o0 = make_float2((acc[mt][nt][0] + bb.x) * esc,
                                    (acc[mt][nt][1] + bb.y) * esc);
            float2 o1 = make_float2((acc[mt][nt][2] + bb.x) * esc,
                                    (acc[mt][nt][3] + bb.y) * esc);
            if (do_round) {
                o0.x = tf32r(o0.x); o0.y = tf32r(o0.y);
                o1.x = tf32r(o1.x); o1.y = tf32r(o1.y);
            }
            *(float2*)&C[(size_t)r0 * D_ + c]       = o0;
            *(float2*)&C[(size_t)(r0 + 8) * D_ + c] = o1;
        }
    }
}

// ---------------------------------------------------------------------------
// Fast exp2 on the FMA pipe. |err| ~2e-6 rel.
// ---------------------------------------------------------------------------
__device__ __forceinline__ float exp2p(float y) {
    y = fmaxf(y, -120.0f);
    float t = y + 12582912.0f;
    int   i = __float_as_int(t);
    float f = y - (t - 12582912.0f);
    float p = 1.3333558e-3f;
    p = fmaf(p, f, 9.6181291e-3f);
    p = fmaf(p, f, 5.5504109e-2f);
    p = fmaf(p, f, 2.4022651e-1f);
    p = fmaf(p, f, 6.9314718e-1f);
    p = fmaf(p, f, 1.0f);
    return __int_as_float(__float_as_int(p) + (i << 23));
}

// ---------------------------------------------------------------------------
// Flash attention, tf32 mma.sync, causal. BM=BN=128, HD=128, 8 warps.
// (R10 design — best measured.) g_q/g_k/g_v pre-rounded (Q pre-scaled).
// Q fragments in registers; K/V cp.async in natural layout (V stride 136
// makes PV B-frags conflict-free); V(t) loads during QK(t), K(t+1) during
// PV(t).
// ---------------------------------------------------------------------------
#define PST 132     // Ps stride (floats)
#define KVT 136     // K/V stride (floats); 136 % 32 == 8

extern __shared__ float satt[];

__global__ __launch_bounds__(256, 1)
void attn_mma(const float* __restrict__ Q, const float* __restrict__ K,
              const float* __restrict__ V, float* __restrict__ O)
{
    float* Ps = satt;                          // 128 x 132
    float* Kb = satt + 128 * PST;              // 128 x 136
    float* Vb = satt + 128 * PST + 128 * KVT;  // 128 x 136
    const uint32_t sbase = smem_u32(satt);
    const uint32_t KbA = sbase + 128u * PST * 4u;
    const uint32_t VbA = KbA + 128u * KVT * 4u;

    const int tid  = threadIdx.x;
    const int w    = tid >> 5;
    const int lane = tid & 31;
    const int g    = lane >> 2;
    const int tg   = lane & 3;
    const int rb   = w * 16;

    const int qb = gridDim.x - 1 - blockIdx.x;   // heavy-first schedule
    const int bh = blockIdx.y;
    const int b  = bh / NH_;
    const int h  = bh % NH_;
    const int q0 = qb * 128;
    const size_t base = (size_t)b * L_ * D_ + (size_t)h * HD_;

    auto load_tile = [&](uint32_t dstA, const float* src) {
        #pragma unroll
        for (int p = 0; p < 16; p++) {
            int idx = p * 256 + tid;
            int r   = idx >> 5;
            int c   = idx & 31;
            CP_ASYNC16(dstA + (uint32_t)(r * KVT + c * 4) * 4u,
                       src + (size_t)r * D_ + c * 4);
        }
    };

    // ---- prologue: stage Q through Kb, pull A-fragments into registers ----
    load_tile(KbA, Q + base + (size_t)q0 * D_);
    CP_COMMIT();
    CP_WAIT0();
    __syncthreads();
    uint32_t qf[16][4];
    #pragma unroll
    for (int ks = 0; ks < 16; ks++) {
        const int kb = ks * 8;
        qf[ks][0] = __float_as_uint(Kb[(rb + g)     * KVT + kb + tg]);
        qf[ks][1] = __float_as_uint(Kb[(rb + g + 8) * KVT + kb + tg]);
        qf[ks][2] = __float_as_uint(Kb[(rb + g)     * KVT + kb + tg + 4]);
        qf[ks][3] = __float_as_uint(Kb[(rb + g + 8) * KVT + kb + tg + 4]);
    }
    __syncthreads();
    load_tile(KbA, K + base);                  // K(0)
    CP_COMMIT();

    float o_[16][4];
    float m0 = -3.0e38f, m1 = -3.0e38f, l0 = 0.0f, l1 = 0.0f;
    #pragma unroll
    for (int nt = 0; nt < 16; nt++)
        #pragma unroll
        for (int e = 0; e < 4; e++) o_[nt][e] = 0.0f;

    for (int t = 0; t <= qb; t++) {
        const int n0 = t * 128;

        __syncthreads();                       // Vb free (prev PV done)
        load_tile(VbA, V + base + (size_t)n0 * D_);
        CP_COMMIT();
        CP_WAIT1();                            // K(t) landed (V(t) in flight)
        __syncthreads();

        // ---- S = Q K^T ----
        float sf[16][4];
        #pragma unroll
        for (int nt = 0; nt < 16; nt++)
            #pragma unroll
            for (int e = 0; e < 4; e++) sf[nt][e] = 0.0f;

        #pragma unroll
        for (int ks = 0; ks < 16; ks++) {
            const int kb = ks * 8;
            #pragma unroll
            for (int nt = 0; nt < 16; nt++) {
                uint32_t bf[2];
                bf[0] = __float_as_uint(Kb[(nt * 8 + g) * KVT + kb + tg]);
                bf[1] = __float_as_uint(Kb[(nt * 8 + g) * KVT + kb + tg + 4]);
                MMA_TF32_16N8K8(sf[nt], qf[ks], bf);
            }
        }

        // ---- causal mask on diagonal tile ----
        if (t == qb) {
            #pragma unroll
            for (int nt = 0; nt < 16; nt++) {
                const int c0 = nt * 8 + 2 * tg;
                const int r0r = rb + g, r1r = rb + g + 8;
                if (r0r < c0)     sf[nt][0] = -1.0e30f;
                if (r0r < c0 + 1) sf[nt][1] = -1.0e30f;
                if (r1r < c0)     sf[nt][2] = -1.0e30f;
                if (r1r < c0 + 1) sf[nt][3] = -1.0e30f;
            }
        }

        // ---- online softmax on fragments ----
        float ml0 = -3.0e38f, ml1 = -3.0e38f;
        #pragma unroll
        for (int nt = 0; nt < 16; nt++) {
            ml0 = fmaxf(ml0, fmaxf(sf[nt][0], sf[nt][1]));
            ml1 = fmaxf(ml1, fmaxf(sf[nt][2], sf[nt][3]));
        }
        ml0 = fmaxf(ml0, __shfl_xor_sync(0xffffffffu, ml0, 1));
        ml0 = fmaxf(ml0, __shfl_xor_sync(0xffffffffu, ml0, 2));
        ml1 = fmaxf(ml1, __shfl_xor_sync(0xffffffffu, ml1, 1));
        ml1 = fmaxf(ml1, __shfl_xor_sync(0xffffffffu, ml1, 2));

        const float mn0 = fmaxf(m0, ml0), mn1 = fmaxf(m1, ml1);
        const float a0 = exp2p(m0 - mn0), a1 = exp2p(m1 - mn1);
        float rs0 = 0.0f, rs1 = 0.0f;
        #pragma unroll
        for (int nt = 0; nt < 16; nt++) {
            float p0 = exp2p(sf[nt][0] - mn0);
            float p1 = exp2p(sf[nt][1] - mn0);
            float p2 = exp2p(sf[nt][2] - mn1);
            float p3 = exp2p(sf[nt][3] - mn1);
            rs0 += p0 + p1; rs1 += p2 + p3;
            *(float2*)&Ps[(rb + g)     * PST + nt * 8 + 2 * tg] =
                make_float2(tf32r(p0), tf32r(p1));
            *(float2*)&Ps[(rb + g + 8) * PST + nt * 8 + 2 * tg] =
                make_float2(tf32r(p2), tf32r(p3));
        }
        rs0 += __shfl_xor_sync(0xffffffffu, rs0, 1);
        rs0 += __shfl_xor_sync(0xffffffffu, rs0, 2);
        rs1 += __shfl_xor_sync(0xffffffffu, rs1, 1);
        rs1 += __shfl_xor_sync(0xffffffffu, rs1, 2);
        l0 = l0 * a0 + rs0; l1 = l1 * a1 + rs1;
        m0 = mn0; m1 = mn1;
        #pragma unroll
        for (int nt = 0; nt < 16; nt++) {
            o_[nt][0] *= a0; o_[nt][1] *= a0;
            o_[nt][2] *= a1; o_[nt][3] *= a1;
        }

        __syncthreads();                       // Kb free (QK reads done)
        if (t < qb) {
            load_tile(KbA, K + base + (size_t)(n0 + 128) * D_);   // K(t+1)
            CP_COMMIT();
            CP_WAIT1();                        // V(t) landed (K(t+1) in flight)
        } else {
            CP_WAIT0();                        // V(t) landed
        }
        __syncthreads();

        // ---- O += P @ V  (V natural; B-frag banks 8tg+g) ----
        #pragma unroll
        for (int ks = 0; ks < 16; ks++) {
            const int kb = ks * 8;
            uint32_t af[4];
            af[0] = __float_as_uint(Ps[(rb + g)     * PST + kb + tg]);
            af[1] = __float_as_uint(Ps[(rb + g + 8) * PST + kb + tg]);
            af[2] = __float_as_uint(Ps[(rb + g)     * PST + kb + tg + 4]);
            af[3] = __float_as_uint(Ps[(rb + g + 8) * PST + kb + tg + 4]);
            #pragma unroll
            for (int nt = 0; nt < 16; nt++) {
                uint32_t bf[2];
                bf[0] = __float_as_uint(Vb[(kb + tg)     * KVT + nt * 8 + g]);
                bf[1] = __float_as_uint(Vb[(kb + tg + 4) * KVT + nt * 8 + g]);
                MMA_TF32_16N8K8(o_[nt], af, bf);
            }
        }
    }

    // ---- epilogue: normalize + tf32-round + write ----
    const float inv0 = 1.0f / l0, inv1 = 1.0f / l1;
    const int gr0 = q0 + rb + g, gr1 = gr0 + 8;
    #pragma unroll
    for (int nt = 0; nt < 16; nt++) {
        const int c = nt * 8 + 2 * tg;
        *(float2*)&O[base + (size_t)gr0 * D_ + c] =
            make_float2(tf32r(o_[nt][0] * inv0), tf32r(o_[nt][1] * inv0));
        *(float2*)&O[base + (size_t)gr1 * D_ + c] =
            make_float2(tf32r(o_[nt][2] * inv1), tf32r(o_[nt][3] * inv1));
    }
}

#define ATTN_SMEM ((128 * PST + 2 * 128 * KVT) * 4)   // 206,848 bytes

// ---------------------------------------------------------------------------
// Launcher
// ---------------------------------------------------------------------------
extern "C" void kernel_launch(void* const* d_in, const int* in_sizes, int n_in,
                              void* d_out, int out_size)
{
    const float* hs = (const float*)d_in[0];
    const float* Wq = (const float*)d_in[1];
    const float* bq = (const float*)d_in[2];
    const float* Wk = (const float*)d_in[3];
    const float* bk = (const float*)d_in[4];
    const float* Wv = (const float*)d_in[5];
    const float* bv = (const float*)d_in[6];
    const float* Wo = (const float*)d_in[7];
    const float* bo = (const float*)d_in[8];
    float* out = (float*)d_out;

    float *q, *k, *v, *attn, *hsr, *wqr, *wkr, *wvr, *wor;
    cudaGetSymbolAddress((void**)&q,    g_q);
    cudaGetSymbolAddress((void**)&k,    g_k);
    cudaGetSymbolAddress((void**)&v,    g_v);
    cudaGetSymbolAddress((void**)&attn, g_attn);
    cudaGetSymbolAddress((void**)&hsr,  g_hsr);
    cudaGetSymbolAddress((void**)&wqr,  g_wqr);
    cudaGetSymbolAddress((void**)&wkr,  g_wkr);
    cudaGetSymbolAddress((void**)&wvr,  g_wvr);
    cudaGetSymbolAddress((void**)&wor,  g_wor);

    // round all GEMM operands to tf32-nearest: ONE launch, z picks tensor
    const int nHS4 = ML_ * D_ / 4;
    const int nW4  = D_ * D_ / 4;
    dim3 gr(1024, 1, 5);
    round_tf32_all<<<gr, 256>>>(hs, hsr, nHS4,
                                Wq, wqr, nW4,
                                Wk, wkr, nW4,
                                Wv, wvr, nW4,
                                Wo, wor, nW4);

    cudaFuncSetAttribute(gemm_tf32mma,
                         cudaFuncAttributeMaxDynamicSharedMemorySize, GEMM_SMEM);

    // fused Q/K/V projection: outputs pre-rounded; Q pre-scaled
    dim3 gqkv(D_ / 128, ML_ / 128, 3);   // (16, 32, 3)
    gemm_tf32mma<<<gqkv, 256, GEMM_SMEM>>>(hsr, wqr, wkr, wvr,
                                           bq, bk, bv, q, k, v,
                                           (float)ATT_QSCALE, 1);

    cudaFuncSetAttribute(attn_mma,
                         cudaFuncAttributeMaxDynamicSharedMemorySize,
                         ATTN_SMEM);
    attn_mma<<<dim3(L_ / 128, BH_), 256, ATTN_SMEM>>>(q, k, v, attn);

    // O-projection: plain fp32 output, no scale, no rounding
    dim3 go(D_ / 128, ML_ / 128, 1);
    gemm_tf32mma<<<go, 256, GEMM_SMEM>>>(attn, wor, wor, wor,
                                         bo, bo, bo, out, out, out,
                                         1.0f, 0);
}